// round 9
// baseline (speedup 1.0000x reference)
#include <cuda_runtime.h>
#include <cuda_bf16.h>

#define NIMG  4
#define KCH   21
#define NPIX  4096      // 64*64
#define TILE  128
#define NT    32        // NPIX / TILE
#define NPAIR 528       // NT*(NT+1)/2
#define HW    16384     // 128*128
#define KSB   32        // g_sb row length (bf16), 64B
#define AROW  80        // seg smem row bytes (conflict-free ldmatrix)
#define FROW  48        // feat smem row bytes (conflict-free ldmatrix)

typedef unsigned long long u64;
typedef unsigned int       u32;
typedef unsigned short     u16;

#define CEXP  (-0.72134752044448170f)   // -0.5 * log2(e)
#define LOG2E ( 1.44269504088896340f)

// ---- device scratch ----
__device__ __nv_bfloat16 g_sb[NIMG][NPIX][KSB]; // seg*roi bf16, k 21..31 zero
__device__ u32   g_fA[NIMG][NPIX][8];           // bf16 row [hi(5),hi(5),lo(5),0]
__device__ u32   g_fB[NIMG][NPIX][8];           // bf16 row [hi(5),lo(5),hi(5),0]
__device__ float g_pq[NIMG][NPIX][2];           // (CEXP*|f|^2, gate)
__device__ float g_partial[NIMG * NPAIR];
__device__ int   g_ctr;

// ---- packed f32x2 helpers ----
__device__ __forceinline__ u64 pk2(float lo, float hi) {
    u64 r; asm("mov.b64 %0, {%1, %2};" : "=l"(r) : "f"(lo), "f"(hi)); return r;
}
__device__ __forceinline__ void unpk2(u64 v, float& lo, float& hi) {
    asm("mov.b64 {%0, %1}, %2;" : "=f"(lo), "=f"(hi) : "l"(v));
}
#define FMA2(d, a, b, c) asm("fma.rn.f32x2 %0, %1, %2, %3;" : "=l"(d) : "l"(a), "l"(b), "l"(c))
#define MUL2(d, a, b)    asm("mul.rn.f32x2 %0, %1, %2;"     : "=l"(d) : "l"(a), "l"(b))
#define ADD2(d, a, b)    asm("add.rn.f32x2 %0, %1, %2;"     : "=l"(d) : "l"(a), "l"(b))
__device__ __forceinline__ float ex2(float x) {
    float r; asm("ex2.approx.f32 %0, %1;" : "=f"(r) : "f"(x)); return r;
}
__device__ __forceinline__ u32 smem_u32(const void* p) {
    u32 a; asm("{ .reg .u64 t; cvta.to.shared.u64 t, %1; cvt.u32.u64 %0, t; }" : "=r"(a) : "l"(p));
    return a;
}
__device__ __forceinline__ u32 bf16pair(float lo, float hi) {   // lo -> bits[0:16)
    u32 r; asm("cvt.rn.bf16x2.f32 %0, %1, %2;" : "=r"(r) : "f"(hi), "f"(lo)); return r;
}
#define LDMX4(r, addr) \
    asm volatile("ldmatrix.sync.aligned.m8n8.x4.shared.b16 {%0,%1,%2,%3}, [%4];" \
        : "=r"((r)[0]), "=r"((r)[1]), "=r"((r)[2]), "=r"((r)[3]) : "r"(addr))
#define MMA16816(d0,d1,d2,d3,a0,a1,a2,a3,b0,b1) \
    asm volatile("mma.sync.aligned.m16n8k16.row.col.f32.bf16.bf16.f32 " \
        "{%0,%1,%2,%3}, {%4,%5,%6,%7}, {%8,%9}, {%0,%1,%2,%3};" \
        : "+f"(d0), "+f"(d1), "+f"(d2), "+f"(d3) \
        : "r"(a0), "r"(a1), "r"(a2), "r"(a3), "r"(b0), "r"(b1))

// ---------------------------------------------------------------------------
// Kernel 1: prep. One block per (n, y-row): coalesced row reads, transpose
// through smem, coalesced bf16 row writes. 256 threads.
// ---------------------------------------------------------------------------
__global__ __launch_bounds__(256) void prep_kernel(const float* __restrict__ images,
                                                   const float* __restrict__ segs,
                                                   const float* __restrict__ rois,
                                                   const int*   __restrict__ labels)
{
    __shared__ float sv[32][64];    // [k][x], k 21..31 zero
    __shared__ float sroi[64];
    int b = blockIdx.x;
    int n = b >> 6, y = b & 63;
    int tid = threadIdx.x;

    for (int i = tid; i < 11 * 64; i += 256) ((float*)sv)[21 * 64 + i] = 0.0f;

    const float* segbase = segs + (size_t)n * KCH * HW + (2 * y) * 128;
    #pragma unroll
    for (int kb = 0; kb < 24; kb += 8) {
        int k = kb + (tid >> 5);
        int t = tid & 31;
        if (k < KCH) {
            const float* sp = segbase + (size_t)k * HW + 4 * t;
            float4 a0 = *(const float4*)sp;
            float4 a1 = *(const float4*)(sp + 128);
            sv[k][2 * t]     = 0.25f * ((a0.x + a0.y) + (a1.x + a1.y));
            sv[k][2 * t + 1] = 0.25f * ((a0.z + a0.w) + (a1.z + a1.w));
        }
    }
    if (tid < 64) sroi[tid] = rois[n * HW + 2 * y * 128 + 2 * tid];
    __syncthreads();

    // ---- seg*roi -> bf16 rows, coalesced (thread = pixel x, chunk c) ----
    {
        int x = tid >> 2, c = tid & 3;
        float roi = sroi[x];
        u32 wb[4];
        #pragma unroll
        for (int j = 0; j < 4; j++) {
            float v0 = sv[c * 8 + 2 * j][x] * roi;
            float v1 = sv[c * 8 + 2 * j + 1][x] * roi;
            wb[j] = bf16pair(v0, v1);
        }
        *(uint4*)&g_sb[n][y * 64 + x][c * 8] = make_uint4(wb[0], wb[1], wb[2], wb[3]);
    }

    // ---- features / gate (thread = pixel x) ----
    if (tid < 64) {
        int x = tid;
        float mx = sv[0][x];
        #pragma unroll
        for (int k = 1; k < KCH; k++) mx = fmaxf(mx, sv[k][x]);
        float roi = sroi[x];
        int p = y * 64 + x;
        int src = 2 * y * 128 + 2 * x;
        int lbl = labels[n * HW + src];
        float gate = fmaxf((lbl == 255) ? 1.0f : (roi - mx), 0.0f);

        const float* ib = images + (size_t)n * 3 * HW + src;
        float f[5];
        f[0] = (float)x * (1.0f / 50.0f);
        f[1] = (float)y * (1.0f / 50.0f);
        f[2] = ib[0]      * (1.0f / 15.0f);
        f[3] = ib[HW]     * (1.0f / 15.0f);
        f[4] = ib[2 * HW] * (1.0f / 15.0f);
        float sq = f[0]*f[0] + f[1]*f[1] + f[2]*f[2] + f[3]*f[3] + f[4]*f[4];
        *(float2*)&g_pq[n][p][0] = make_float2(CEXP * sq, gate);

        u16 h[5], l[5];
        #pragma unroll
        for (int d = 0; d < 5; d++) {
            __nv_bfloat16 hb = __float2bfloat16(f[d]);
            __nv_bfloat16 lb = __float2bfloat16(f[d] - __bfloat162float(hb));
            h[d] = *(u16*)&hb; l[d] = *(u16*)&lb;
        }
        // A row: hi(5) hi(5) lo(5) 0  |  B row: hi(5) lo(5) hi(5) 0
        u32 aw[8], bw[8];
        aw[0] = h[0] | (u32)h[1] << 16;  aw[1] = h[2] | (u32)h[3] << 16;
        aw[2] = h[4] | (u32)h[0] << 16;  aw[3] = h[1] | (u32)h[2] << 16;
        aw[4] = h[3] | (u32)h[4] << 16;  aw[5] = l[0] | (u32)l[1] << 16;
        aw[6] = l[2] | (u32)l[3] << 16;  aw[7] = l[4];
        bw[0] = h[0] | (u32)h[1] << 16;  bw[1] = h[2] | (u32)h[3] << 16;
        bw[2] = h[4] | (u32)l[0] << 16;  bw[3] = l[1] | (u32)l[2] << 16;
        bw[4] = l[3] | (u32)l[4] << 16;  bw[5] = h[0] | (u32)h[1] << 16;
        bw[6] = h[2] | (u32)h[3] << 16;  bw[7] = h[4];
        *(uint4*)&g_fA[n][p][0] = make_uint4(aw[0], aw[1], aw[2], aw[3]);
        *(uint4*)&g_fA[n][p][4] = make_uint4(aw[4], aw[5], aw[6], aw[7]);
        *(uint4*)&g_fB[n][p][0] = make_uint4(bw[0], bw[1], bw[2], bw[3]);
        *(uint4*)&g_fB[n][p][4] = make_uint4(bw[4], bw[5], bw[6], bw[7]);
    }
}

// ---------------------------------------------------------------------------
// Kernel 2: per tile-pair (128x128): seg GEMM (K=32) AND feature-dot GEMM
// (K=16, hi/lo split) on tensor pipe; scalar work = exp + gating only.
// 16 warps = 8 m-strips x 2 n-halves.
// ---------------------------------------------------------------------------
__global__ __launch_bounds__(512, 2) void energy_kernel(float* __restrict__ out)
{
    __shared__ __align__(16) char sA [TILE * AROW];   // seg p
    __shared__ __align__(16) char sB [TILE * AROW];   // seg q
    __shared__ __align__(16) char sFA[TILE * FROW];   // feat p (A layout)
    __shared__ __align__(16) char sFB[TILE * FROW];   // feat q (B layout)
    __shared__ __align__(16) u64  qsg[64][2];         // (sqs pair, gate pair)
    __shared__ float red[16];
    __shared__ int   lastflag;

    int t = blockIdx.x;
    int n = blockIdx.y;
    int tid = threadIdx.x;
    int w = tid >> 5, lane = tid & 31;

    int ti = 0, rem = t;
    while (rem >= NT - ti) { rem -= NT - ti; ti++; }
    int tj = ti + rem;
    int p0 = ti * TILE, q0 = tj * TILE;
    bool diag = (ti == tj);

    // ---- fill smem ----
    {
        int r = tid >> 2, c = tid & 3;
        *(uint4*)(sA + r * AROW + c * 16) = *(const uint4*)&g_sb[n][p0 + r][c * 8];
        *(uint4*)(sB + r * AROW + c * 16) = *(const uint4*)&g_sb[n][q0 + r][c * 8];
    }
    if (tid < 256) {
        int r = tid >> 1, h = tid & 1;
        *(uint4*)(sFA + r * FROW + h * 16) = *(const uint4*)&g_fA[n][p0 + r][h * 4];
    } else {
        int r = (tid - 256) >> 1, h = tid & 1;
        *(uint4*)(sFB + r * FROW + h * 16) = *(const uint4*)&g_fB[n][q0 + r][h * 4];
    }
    if (tid < 64) {
        float2 e = *(const float2*)&g_pq[n][q0 + 2 * tid][0];
        float2 o = *(const float2*)&g_pq[n][q0 + 2 * tid + 1][0];
        qsg[tid][0] = pk2(e.x, o.x);
        qsg[tid][1] = pk2(diag ? 0.0f : e.y, diag ? 0.0f : o.y);
    }
    __syncthreads();

    int mstrip = w >> 1, nhalf = w & 1, lm4 = lane & 3;
    u32 sAu = smem_u32(sA), sBu = smem_u32(sB);
    u32 sFAu = smem_u32(sFA), sFBu = smem_u32(sFB);

    // A fragments (seg K=32, feat K=16)
    u32 afr[2][4], afeat[4];
    {
        int arow = mstrip * 16 + (lane & 7) + ((lane >> 3) & 1) * 8;
        u32 aaddr = sAu + arow * AROW + (lane >> 4) * 16;
        LDMX4(afr[0], aaddr);
        LDMX4(afr[1], aaddr + 32);
        u32 faddr = sFAu + arow * FROW + ((lane >> 4) & 1) * 16;
        LDMX4(afeat, faddr);
    }
    u32 baddr  = sBu  + (nhalf * 64 + (lane & 7)) * AROW + (lane >> 3) * 16;
    u32 fbaddr = sFBu + (nhalf * 64 + (lane & 7) + ((lane >> 4) & 1) * 8) * FROW
                      + ((lane >> 3) & 1) * 16;

    // p-side scalars (packed broadcast)
    int rowA0 = mstrip * 16 + (lane >> 2);
    u64 sps[2], gp2[2];
    {
        float2 pp0 = *(const float2*)&g_pq[n][p0 + rowA0][0];
        float2 pp1 = *(const float2*)&g_pq[n][p0 + rowA0 + 8][0];
        sps[0] = pk2(pp0.x, pp0.x); gp2[0] = pk2(pp0.y, pp0.y);
        sps[1] = pk2(pp1.x, pp1.x); gp2[1] = pk2(pp1.y, pp1.y);
    }
    u64 l2e = pk2(LOG2E, LOG2E);
    u64 acc2 = 0ull;
    u32 bfeat[4];

    #pragma unroll
    for (int tt = 0; tt < 8; tt++) {
        u32 bfr[4];
        LDMX4(bfr, baddr + tt * (8 * AROW));
        if ((tt & 1) == 0) LDMX4(bfeat, fbaddr + tt * (8 * FROW));
        u32 b0f = (tt & 1) ? bfeat[2] : bfeat[0];
        u32 b1f = (tt & 1) ? bfeat[3] : bfeat[1];

        float d0 = 0.f, d1 = 0.f, d2_ = 0.f, d3 = 0.f;
        MMA16816(d0, d1, d2_, d3, afr[0][0], afr[0][1], afr[0][2], afr[0][3], bfr[0], bfr[1]);
        MMA16816(d0, d1, d2_, d3, afr[1][0], afr[1][1], afr[1][2], afr[1][3], bfr[2], bfr[3]);
        float e0 = 0.f, e1 = 0.f, e2 = 0.f, e3 = 0.f;
        MMA16816(e0, e1, e2, e3, afeat[0], afeat[1], afeat[2], afeat[3], b0f, b1f);

        ulonglong2 qv = *(const ulonglong2*)&qsg[nhalf * 32 + tt * 4 + lm4][0];

        #pragma unroll
        for (int r = 0; r < 2; r++) {
            u64 dotp = r ? pk2(e2, e3) : pk2(e0, e1);
            u64 s2; ADD2(s2, sps[r], qv.x);
            u64 t2; FMA2(t2, dotp, l2e, s2);       // CEXP*d2 (<= ~0)
            float tlo, thi; unpk2(t2, tlo, thi);
            u64 ee = pk2(ex2(fminf(tlo, 0.0f)), ex2(fminf(thi, 0.0f)));
            u64 cf; ADD2(cf, gp2[r], qv.y);        // q-gate zeroed on diag
            u64 wv; MUL2(wv, ee, cf);
            u64 cc = r ? pk2(d2_, d3) : pk2(d0, d1);
            FMA2(acc2, wv, cc, acc2);
        }
    }

    float alo, ahi; unpk2(acc2, alo, ahi);
    float acc = alo + ahi;

    // ---- block reduction, deterministic per-CTA partial ----
    #pragma unroll
    for (int o = 16; o > 0; o >>= 1) acc += __shfl_down_sync(0xffffffffu, acc, o);
    if (lane == 0) red[w] = acc;
    __syncthreads();
    if (tid == 0) {
        float s = 0.0f;
        #pragma unroll
        for (int v = 0; v < 16; v++) s += red[v];
        g_partial[n * NPAIR + t] = s;
        __threadfence();
        int v = atomicAdd(&g_ctr, 1);
        lastflag = (v == NIMG * NPAIR - 1);
    }
    __syncthreads();

    if (lastflag) {
        float s = 0.0f;
        for (int i = tid; i < NIMG * NPAIR; i += 512) s += g_partial[i];
        #pragma unroll
        for (int o = 16; o > 0; o >>= 1) s += __shfl_down_sync(0xffffffffu, s, o);
        if (lane == 0) red[w] = s;
        __syncthreads();
        if (tid == 0) {
            float tot = 0.0f;
            #pragma unroll
            for (int v = 0; v < 16; v++) tot += red[v];
            out[0] = tot * (-1e-7f / (float)NIMG);   // WEIGHT * (-sum / N)
            g_ctr = 0;                               // reset for graph replay
        }
    }
}

// ---------------------------------------------------------------------------
extern "C" void kernel_launch(void* const* d_in, const int* in_sizes, int n_in,
                              void* d_out, int out_size)
{
    const float* images = (const float*)d_in[0];
    const float* segs   = (const float*)d_in[1];
    const float* rois   = (const float*)d_in[2];
    const int*   labels = (const int*)  d_in[3];

    prep_kernel<<<NIMG * 64, 256>>>(images, segs, rois, labels);
    dim3 grid(NPAIR, NIMG);
    energy_kernel<<<grid, 512>>>((float*)d_out);
}

// round 10
// speedup vs baseline: 1.7823x; 1.7823x over previous
#include <cuda_runtime.h>
#include <cuda_bf16.h>

#define NIMG  4
#define KCH   21
#define NPIX  4096      // 64*64
#define TILE  128
#define NT    32        // max tiles
#define NPAIR 528       // max tile-pairs (grid size)
#define HW    16384     // 128*128
#define KPAD  64        // bf16 K row padding in global scratch
#define ROWW  40        // smem tile row width in bf16 (80B, conflict-free)
#define QROW  10        // qpk row stride in u64 (80B, 16B-aligned, conflict-free)

typedef unsigned long long u64;
typedef unsigned int       u32;

#define CEXP  (-0.72134752044448170f)   // -0.5 * log2(e)
#define LOG2E ( 1.44269504088896340f)

// ---- device scratch (rows [NPIX..NPIX+8) are never written => stay zero) ----
__device__ __nv_bfloat16 g_sb [NIMG][NPIX + 8][KPAD];
__device__ float         g_ppk[NIMG][NPIX + 8][8];   // f0..f4, CEXP*|f|^2, gate, 0
__device__ int           g_idx[NIMG][NPIX];          // compacted roi=1 pixel ids (+ sentinel pad)
__device__ int           g_nt [NIMG];                // tiles per image
__device__ float         g_partial[NIMG * NPAIR];
__device__ int           g_ctr;

// ---- packed f32x2 helpers ----
__device__ __forceinline__ u64 pk2(float lo, float hi) {
    u64 r; asm("mov.b64 %0, {%1, %2};" : "=l"(r) : "f"(lo), "f"(hi)); return r;
}
__device__ __forceinline__ void unpk2(u64 v, float& lo, float& hi) {
    asm("mov.b64 {%0, %1}, %2;" : "=f"(lo), "=f"(hi) : "l"(v));
}
#define FMA2(d, a, b, c) asm("fma.rn.f32x2 %0, %1, %2, %3;" : "=l"(d) : "l"(a), "l"(b), "l"(c))
#define MUL2(d, a, b)    asm("mul.rn.f32x2 %0, %1, %2;"     : "=l"(d) : "l"(a), "l"(b))
#define ADD2(d, a, b)    asm("add.rn.f32x2 %0, %1, %2;"     : "=l"(d) : "l"(a), "l"(b))
__device__ __forceinline__ float ex2(float x) {
    float r; asm("ex2.approx.f32 %0, %1;" : "=f"(r) : "f"(x)); return r;
}
__device__ __forceinline__ u32 smem_u32(const void* p) {
    u32 a; asm("{ .reg .u64 t; cvta.to.shared.u64 t, %1; cvt.u32.u64 %0, t; }" : "=r"(a) : "l"(p));
    return a;
}
#define LDMX4(r, addr) \
    asm volatile("ldmatrix.sync.aligned.m8n8.x4.shared.b16 {%0,%1,%2,%3}, [%4];" \
        : "=r"((r)[0]), "=r"((r)[1]), "=r"((r)[2]), "=r"((r)[3]) : "r"(addr))
#define MMA16816(d0,d1,d2,d3,a0,a1,a2,a3,b0,b1) \
    asm volatile("mma.sync.aligned.m16n8k16.row.col.f32.bf16.bf16.f32 " \
        "{%0,%1,%2,%3}, {%4,%5,%6,%7}, {%8,%9}, {%0,%1,%2,%3};" \
        : "+f"(d0), "+f"(d1), "+f"(d2), "+f"(d3) \
        : "r"(a0), "r"(a1), "r"(a2), "r"(a3), "r"(b0), "r"(b1))

// ---------------------------------------------------------------------------
// Kernel 1: warp-per-2-pixels prep (R8 version, proven).
// ---------------------------------------------------------------------------
__global__ __launch_bounds__(256) void prep_kernel(const float* __restrict__ images,
                                                   const float* __restrict__ segs,
                                                   const float* __restrict__ rois,
                                                   const int*   __restrict__ labels)
{
    int gw   = (blockIdx.x * blockDim.x + threadIdx.x) >> 5;   // pixel-pair id
    int lane = threadIdx.x & 31;
    int n  = gw >> 11;
    int pr = gw & 2047;
    int y  = pr >> 5;
    int xh = pr & 31;
    int p_e = y * 64 + 2 * xh;
    int src = (2 * y) * 128 + 4 * xh;

    float4 roi4 = make_float4(0.f, 0.f, 0.f, 0.f);
    if (lane == 0) roi4 = *(const float4*)(rois + n * HW + src);
    float roi_e = __shfl_sync(0xffffffffu, roi4.x, 0);
    float roi_o = __shfl_sync(0xffffffffu, roi4.z, 0);

    float v_e = 0.0f, v_o = 0.0f;
    if (lane < KCH) {
        const float* sp = segs + ((size_t)(n * KCH + lane)) * HW + src;
        float4 a0 = *(const float4*)(sp);
        float4 a1 = *(const float4*)(sp + 128);
        v_e = 0.25f * ((a0.x + a0.y) + (a1.x + a1.y));   // exact bilinear 2x
        v_o = 0.25f * ((a0.z + a0.w) + (a1.z + a1.w));
    }
    float me = v_e, mo = v_o;
    #pragma unroll
    for (int o = 16; o > 0; o >>= 1) {
        me = fmaxf(me, __shfl_xor_sync(0xffffffffu, me, o));
        mo = fmaxf(mo, __shfl_xor_sync(0xffffffffu, mo, o));
    }

    char* row_e = (char*)&g_sb[n][p_e][0];
    char* row_o = row_e + KPAD * 2;
    if (lane < KCH) {
        *(__nv_bfloat16*)(row_e + 2 * lane) = __float2bfloat16(v_e * roi_e);
        *(__nv_bfloat16*)(row_o + 2 * lane) = __float2bfloat16(v_o * roi_o);
    }
    if (lane == 21) {
        *(unsigned short*)(row_e + 42) = 0;
        *(unsigned short*)(row_o + 42) = 0;
    }
    if (lane >= 22 && lane < 27) {
        *(u32*)(row_e + 44 + 4 * (lane - 22)) = 0u;
        *(u32*)(row_o + 44 + 4 * (lane - 22)) = 0u;
    }

    if (lane < 2) {
        float roi = lane ? roi_o : roi_e;
        float mx  = lane ? mo    : me;
        int s     = src + 2 * lane;
        int lbl = labels[n * HW + s];
        float gate = (lbl == 255) ? 1.0f : (roi - mx);
        gate = fmaxf(gate, 0.0f);
        const float* ib = images + (size_t)n * 3 * HW + s;
        float fx = (float)(2 * xh + lane) * (1.0f / 50.0f);
        float fy = (float)y * (1.0f / 50.0f);
        float r  = ib[0]      * (1.0f / 15.0f);
        float g  = ib[HW]     * (1.0f / 15.0f);
        float b  = ib[2 * HW] * (1.0f / 15.0f);
        float sq = CEXP * (fx*fx + fy*fy + r*r + g*g + b*b);
        float4* pw = (float4*)&g_ppk[n][p_e + lane][0];
        pw[0] = make_float4(fx, fy, r, g);
        pw[1] = make_float4(b, sq, gate, 0.0f);
    }
}

// ---------------------------------------------------------------------------
// Kernel 1b: deterministic compaction of roi=1 pixels per image.
// One block per image, 256 threads, 16 pixels each, ordered prefix scan.
// ---------------------------------------------------------------------------
__global__ __launch_bounds__(256) void compact_kernel(const float* __restrict__ rois)
{
    __shared__ int warp_sums[8];
    __shared__ int s_cnt;
    int n = blockIdx.x;
    int tid = threadIdx.x;
    int lane = tid & 31, w = tid >> 5;
    int pbase = tid * 16;

    u32 mask = 0; int c = 0;
    #pragma unroll
    for (int i = 0; i < 16; i++) {
        int p = pbase + i;
        int y = p >> 6, x = p & 63;
        float r = rois[n * HW + (2 * y) * 128 + 2 * x];
        if (r > 0.5f) { mask |= (1u << i); c++; }
    }
    int sc = c;
    #pragma unroll
    for (int o = 1; o < 32; o <<= 1) {
        int v = __shfl_up_sync(0xffffffffu, sc, o);
        if (lane >= o) sc += v;
    }
    if (lane == 31) warp_sums[w] = sc;
    __syncthreads();
    int wb = 0;
    #pragma unroll
    for (int i = 0; i < 8; i++) if (i < w) wb += warp_sums[i];
    int pos = wb + sc - c;
    #pragma unroll
    for (int i = 0; i < 16; i++)
        if (mask & (1u << i)) g_idx[n][pos++] = pbase + i;
    if (tid == 255) s_cnt = wb + sc;
    __syncthreads();
    int cnt = s_cnt;
    int nt = (cnt + 127) >> 7;
    for (int j = cnt + tid; j < nt * 128; j += 256) g_idx[n][j] = NPIX;  // sentinel zero row
    if (tid == 0) g_nt[n] = nt;
}

// ---------------------------------------------------------------------------
// Kernel 2: tile-pair energy over COMPACTED pixels. R8 math core.
// ---------------------------------------------------------------------------
__global__ __launch_bounds__(512, 2) void energy_kernel(float* __restrict__ out)
{
    __shared__ __align__(16) char sA[TILE * ROWW * 2];
    __shared__ __align__(16) char sB[TILE * ROWW * 2];
    __shared__ __align__(16) u64  qpk[64][QROW];
    __shared__ float red[16];
    __shared__ int   lastflag;

    int t = blockIdx.x;
    int n = blockIdx.y;
    int tid = threadIdx.x;
    int w = tid >> 5, lane = tid & 31;

    int nt = g_nt[n];
    int pairs = nt * (nt + 1) / 2;
    bool active = (t < pairs);

    if (active) {
        // triangular decode (uniform)
        int ti = 0, rem = t;
        while (rem >= nt - ti) { rem -= nt - ti; ti++; }
        int tj = ti + rem;
        int p0 = ti * TILE, q0 = tj * TILE;
        bool diag = (ti == tj);

        // ---- gathered tile fill ----
        {
            int r = tid >> 2, c = tid & 3;
            int ip = g_idx[n][p0 + r];
            int iq = g_idx[n][q0 + r];
            *(uint4*)(sA + r * (ROWW * 2) + c * 16) = *(const uint4*)&g_sb[n][ip][c * 8];
            *(uint4*)(sB + r * (ROWW * 2) + c * 16) = *(const uint4*)&g_sb[n][iq][c * 8];
        }
        // ---- pair-packed q features; diag zeroes the q-gate ----
        {
            float* qf = (float*)qpk;
            #pragma unroll
            for (int it = 0; it < 2; it++) {
                int idx = tid + it * 512;
                int q = idx >> 3, d = idx & 7;
                int iq = g_idx[n][q0 + q];
                float v = g_ppk[n][iq][d];
                if (d == 6 && diag) v = 0.0f;
                qf[(q >> 1) * (QROW * 2) + d * 2 + (q & 1)] = v;
            }
        }
        __syncthreads();

        int mstrip = w >> 1, nhalf = w & 1, lm4 = lane & 3;
        u32 sAu = smem_u32(sA), sBu = smem_u32(sB);

        u32 afr[2][4];
        {
            int arow = mstrip * 16 + (lane & 7) + ((lane >> 3) & 1) * 8;
            u32 aaddr = sAu + arow * (ROWW * 2) + (lane >> 4) * 16;
            LDMX4(afr[0], aaddr);
            LDMX4(afr[1], aaddr + 32);
        }
        u32 baddr = sBu + (nhalf * 64 + (lane & 7)) * (ROWW * 2) + (lane >> 3) * 16;

        // p-side features via gathered index
        int rowA0 = mstrip * 16 + (lane >> 2);
        int ip0 = g_idx[n][p0 + rowA0];
        int ip1 = g_idx[n][p0 + rowA0 + 8];
        u64 f0[2], f1[2], f2[2], f3[2], f4[2], sps[2], gp2[2];
        #pragma unroll
        for (int r = 0; r < 2; r++) {
            const float4* pf = (const float4*)&g_ppk[n][r ? ip1 : ip0][0];
            float4 pa = pf[0], pb = pf[1];
            f0[r] = pk2(pa.x, pa.x); f1[r] = pk2(pa.y, pa.y); f2[r] = pk2(pa.z, pa.z);
            f3[r] = pk2(pa.w, pa.w); f4[r] = pk2(pb.x, pb.x);
            sps[r] = pk2(pb.y, pb.y); gp2[r] = pk2(pb.z, pb.z);
        }
        u64 l2e = pk2(LOG2E, LOG2E);
        const char* qb = (const char*)qpk + (nhalf * 32 + lm4) * (QROW * 8);

        u64 accA = 0ull, accB = 0ull;

        #pragma unroll
        for (int tt = 0; tt < 8; tt++) {
            u32 bfr[4];
            LDMX4(bfr, baddr + tt * (8 * ROWW * 2));

            float d0 = 0.f, d1 = 0.f, d2_ = 0.f, d3 = 0.f;
            MMA16816(d0, d1, d2_, d3, afr[0][0], afr[0][1], afr[0][2], afr[0][3], bfr[0], bfr[1]);
            MMA16816(d0, d1, d2_, d3, afr[1][0], afr[1][1], afr[1][2], afr[1][3], bfr[2], bfr[3]);

            const char* qp = qb + tt * (4 * QROW * 8);
            ulonglong2 q01 = *(const ulonglong2*)(qp);
            ulonglong2 q23 = *(const ulonglong2*)(qp + 16);
            ulonglong2 q45 = *(const ulonglong2*)(qp + 32);
            ulonglong2 q67 = *(const ulonglong2*)(qp + 48);

            #pragma unroll
            for (int r = 0; r < 2; r++) {
                u64 dot;
                MUL2(dot, f0[r], q01.x);
                FMA2(dot, f1[r], q01.y, dot);
                FMA2(dot, f2[r], q23.x, dot);
                FMA2(dot, f3[r], q23.y, dot);
                FMA2(dot, f4[r], q45.x, dot);
                u64 s2; ADD2(s2, sps[r], q45.y);
                u64 t2; FMA2(t2, dot, l2e, s2);   // CEXP*d2 (<= ~1e-4)
                float tlo, thi; unpk2(t2, tlo, thi);
                u64 ee = pk2(ex2(tlo), ex2(thi)); // no clamp: d2 >= -eps only
                u64 cf; ADD2(cf, gp2[r], q67.x);
                u64 wv; MUL2(wv, ee, cf);
                u64 cc = r ? pk2(d2_, d3) : pk2(d0, d1);
                if (r) { FMA2(accB, wv, cc, accB); }
                else   { FMA2(accA, wv, cc, accA); }
            }
        }

        u64 acc2; ADD2(acc2, accA, accB);
        float alo, ahi; unpk2(acc2, alo, ahi);
        float acc = alo + ahi;

        #pragma unroll
        for (int o = 16; o > 0; o >>= 1) acc += __shfl_down_sync(0xffffffffu, acc, o);
        if (lane == 0) red[w] = acc;
        __syncthreads();
        if (tid == 0) {
            float s = 0.0f;
            #pragma unroll
            for (int v = 0; v < 16; v++) s += red[v];
            g_partial[n * NPAIR + t] = s;
            __threadfence();
            int v = atomicAdd(&g_ctr, 1);
            lastflag = (v == NIMG * NPAIR - 1);
        }
        __syncthreads();
    } else {
        if (tid == 0) {
            __threadfence();
            int v = atomicAdd(&g_ctr, 1);
            lastflag = (v == NIMG * NPAIR - 1);
        }
        __syncthreads();
    }

    // ---- last CTA: deterministic final reduction + scaling ----
    if (lastflag) {
        float s = 0.0f;
        for (int i = tid; i < NIMG * NPAIR; i += 512) s += g_partial[i];
        #pragma unroll
        for (int o = 16; o > 0; o >>= 1) s += __shfl_down_sync(0xffffffffu, s, o);
        if (lane == 0) red[w] = s;
        __syncthreads();
        if (tid == 0) {
            float tot = 0.0f;
            #pragma unroll
            for (int v = 0; v < 16; v++) tot += red[v];
            out[0] = tot * (-1e-7f / (float)NIMG);   // WEIGHT * (-sum / N)
            g_ctr = 0;                               // reset for graph replay
        }
    }
}

// ---------------------------------------------------------------------------
extern "C" void kernel_launch(void* const* d_in, const int* in_sizes, int n_in,
                              void* d_out, int out_size)
{
    const float* images = (const float*)d_in[0];
    const float* segs   = (const float*)d_in[1];
    const float* rois   = (const float*)d_in[2];
    const int*   labels = (const int*)  d_in[3];

    prep_kernel<<<(NIMG * NPIX / 2) * 32 / 256, 256>>>(images, segs, rois, labels);
    compact_kernel<<<NIMG, 256>>>(rois);
    dim3 grid(NPAIR, NIMG);
    energy_kernel<<<grid, 512>>>((float*)d_out);
}

// round 11
// speedup vs baseline: 2.0660x; 1.1592x over previous
#include <cuda_runtime.h>
#include <cuda_bf16.h>

#define NIMG  4
#define KCH   21
#define NPIX  4096      // 64*64
#define TILE  128
#define NT    32        // max tiles
#define NPAIR 528       // max tile-pairs (grid size)
#define HW    16384     // 128*128
#define KPAD  64        // bf16 K row padding in global scratch
#define ROWW  40        // smem tile row width in bf16 (80B, conflict-free)
#define QROW  10        // qpk row stride in u64 (80B, 16B-aligned, conflict-free)
#define SVW   33        // transpose smem row stride (floats)

typedef unsigned long long u64;
typedef unsigned int       u32;

#define CEXP  (-0.72134752044448170f)   // -0.5 * log2(e)
#define LOG2E ( 1.44269504088896340f)

// ---- device scratch (rows [NPIX..NPIX+8) are never written => stay zero) ----
__device__ __nv_bfloat16 g_sb [NIMG][NPIX + 8][KPAD];
__device__ float         g_ppk[NIMG][NPIX + 8][8];   // f0..f4, CEXP*|f|^2, gate, 0
__device__ int           g_idx[NIMG][NPIX];          // compacted roi=1 pixel ids (+ sentinel pad)
__device__ int           g_nt [NIMG];                // tiles per image
__device__ float         g_partial[NIMG * NPAIR];
__device__ int           g_ctr;

// ---- packed f32x2 helpers ----
__device__ __forceinline__ u64 pk2(float lo, float hi) {
    u64 r; asm("mov.b64 %0, {%1, %2};" : "=l"(r) : "f"(lo), "f"(hi)); return r;
}
__device__ __forceinline__ void unpk2(u64 v, float& lo, float& hi) {
    asm("mov.b64 {%0, %1}, %2;" : "=f"(lo), "=f"(hi) : "l"(v));
}
#define FMA2(d, a, b, c) asm("fma.rn.f32x2 %0, %1, %2, %3;" : "=l"(d) : "l"(a), "l"(b), "l"(c))
#define MUL2(d, a, b)    asm("mul.rn.f32x2 %0, %1, %2;"     : "=l"(d) : "l"(a), "l"(b))
#define ADD2(d, a, b)    asm("add.rn.f32x2 %0, %1, %2;"     : "=l"(d) : "l"(a), "l"(b))
__device__ __forceinline__ float ex2(float x) {
    float r; asm("ex2.approx.f32 %0, %1;" : "=f"(r) : "f"(x)); return r;
}
__device__ __forceinline__ u32 smem_u32(const void* p) {
    u32 a; asm("{ .reg .u64 t; cvta.to.shared.u64 t, %1; cvt.u32.u64 %0, t; }" : "=r"(a) : "l"(p));
    return a;
}
__device__ __forceinline__ u32 bf16pair(float lo, float hi) {   // lo -> bits[0:16)
    u32 r; asm("cvt.rn.bf16x2.f32 %0, %1, %2;" : "=r"(r) : "f"(hi), "f"(lo)); return r;
}
#define LDMX4(r, addr) \
    asm volatile("ldmatrix.sync.aligned.m8n8.x4.shared.b16 {%0,%1,%2,%3}, [%4];" \
        : "=r"((r)[0]), "=r"((r)[1]), "=r"((r)[2]), "=r"((r)[3]) : "r"(addr))
#define MMA16816(d0,d1,d2,d3,a0,a1,a2,a3,b0,b1) \
    asm volatile("mma.sync.aligned.m16n8k16.row.col.f32.bf16.bf16.f32 " \
        "{%0,%1,%2,%3}, {%4,%5,%6,%7}, {%8,%9}, {%0,%1,%2,%3};" \
        : "+f"(d0), "+f"(d1), "+f"(d2), "+f"(d3) \
        : "r"(a0), "r"(a1), "r"(a2), "r"(a3), "r"(b0), "r"(b1))

// ---------------------------------------------------------------------------
// Kernel 1 (fused): blocks [0,256): coalesced transpose prep, one block per
// (n, y-row). blocks [256,260): per-image roi compaction (independent input).
// ---------------------------------------------------------------------------
__global__ __launch_bounds__(256) void prep_kernel(const float* __restrict__ images,
                                                   const float* __restrict__ segs,
                                                   const float* __restrict__ rois,
                                                   const int*   __restrict__ labels)
{
    __shared__ float sv[64][SVW];   // [x][k], k 21..31 zero
    __shared__ float sroi[64];
    __shared__ int   warp_sums[8];
    __shared__ int   s_cnt;

    int b = blockIdx.x;
    int tid = threadIdx.x;

    if (b < NIMG * 64) {
        // ================= PREP: one (n, y) row =================
        int n = b >> 6, y = b & 63;

        // zero k-pad columns 21..32 (per x)
        for (int i = tid; i < 64 * 11; i += 256) {
            int x = i / 11, k = 21 + (i % 11);
            sv[x][k] = 0.0f;
        }

        const float* segbase = segs + (size_t)n * KCH * HW + (2 * y) * 128;
        #pragma unroll
        for (int kb = 0; kb < 24; kb += 8) {
            int k = kb + (tid >> 5);
            int t = tid & 31;
            if (k < KCH) {
                const float* sp = segbase + (size_t)k * HW + 4 * t;
                float4 a0 = *(const float4*)sp;
                float4 a1 = *(const float4*)(sp + 128);
                // exact same expression as R10 (bit-identical avg)
                sv[2 * t][k]     = 0.25f * ((a0.x + a0.y) + (a1.x + a1.y));
                sv[2 * t + 1][k] = 0.25f * ((a0.z + a0.w) + (a1.z + a1.w));
            }
        }
        if (tid < 64) sroi[tid] = rois[n * HW + 2 * y * 128 + 2 * tid];
        __syncthreads();

        // ---- seg*roi -> bf16 rows, coalesced (thread = pixel x, chunk c) ----
        {
            int x = tid >> 2, c = tid & 3;
            float roi = sroi[x];
            u32 wb[4];
            #pragma unroll
            for (int j = 0; j < 4; j++) {
                float v0 = sv[x][c * 8 + 2 * j]     * roi;
                float v1 = sv[x][c * 8 + 2 * j + 1] * roi;
                wb[j] = bf16pair(v0, v1);
            }
            *(uint4*)&g_sb[n][y * 64 + x][c * 8] = make_uint4(wb[0], wb[1], wb[2], wb[3]);
        }

        // ---- features / gate (thread = pixel x) ----
        if (tid < 64) {
            int x = tid;
            float mx = sv[x][0];
            #pragma unroll
            for (int k = 1; k < KCH; k++) mx = fmaxf(mx, sv[x][k]);
            float roi = sroi[x];
            int p = y * 64 + x;
            int src = 2 * y * 128 + 2 * x;
            int lbl = labels[n * HW + src];
            float gate = fmaxf((lbl == 255) ? 1.0f : (roi - mx), 0.0f);

            const float* ib = images + (size_t)n * 3 * HW + src;
            float fx = (float)x * (1.0f / 50.0f);
            float fy = (float)y * (1.0f / 50.0f);
            float r  = ib[0]      * (1.0f / 15.0f);
            float g  = ib[HW]     * (1.0f / 15.0f);
            float bl = ib[2 * HW] * (1.0f / 15.0f);
            float sq = CEXP * (fx*fx + fy*fy + r*r + g*g + bl*bl);
            float4* pw = (float4*)&g_ppk[n][p][0];
            pw[0] = make_float4(fx, fy, r, g);
            pw[1] = make_float4(bl, sq, gate, 0.0f);
        }
    } else {
        // ================= COMPACT: one image =================
        int n = b - NIMG * 64;
        int lane = tid & 31, w = tid >> 5;
        int pbase = tid * 16;

        u32 mask = 0; int c = 0;
        #pragma unroll
        for (int i = 0; i < 16; i++) {
            int p = pbase + i;
            int y = p >> 6, x = p & 63;
            float r = rois[n * HW + (2 * y) * 128 + 2 * x];
            if (r > 0.5f) { mask |= (1u << i); c++; }
        }
        int sc = c;
        #pragma unroll
        for (int o = 1; o < 32; o <<= 1) {
            int v = __shfl_up_sync(0xffffffffu, sc, o);
            if (lane >= o) sc += v;
        }
        if (lane == 31) warp_sums[w] = sc;
        __syncthreads();
        int wb = 0;
        #pragma unroll
        for (int i = 0; i < 8; i++) if (i < w) wb += warp_sums[i];
        int pos = wb + sc - c;
        #pragma unroll
        for (int i = 0; i < 16; i++)
            if (mask & (1u << i)) g_idx[n][pos++] = pbase + i;
        if (tid == 255) s_cnt = wb + sc;
        __syncthreads();
        int cnt = s_cnt;
        int nt = (cnt + 127) >> 7;
        for (int j = cnt + tid; j < nt * 128; j += 256) g_idx[n][j] = NPIX;  // sentinel
        if (tid == 0) g_nt[n] = nt;
    }
}

// ---------------------------------------------------------------------------
// Kernel 2: tile-pair energy over COMPACTED pixels (R10 core, unchanged).
// ---------------------------------------------------------------------------
__global__ __launch_bounds__(512, 2) void energy_kernel(float* __restrict__ out)
{
    __shared__ __align__(16) char sA[TILE * ROWW * 2];
    __shared__ __align__(16) char sB[TILE * ROWW * 2];
    __shared__ __align__(16) u64  qpk[64][QROW];
    __shared__ float red[16];
    __shared__ int   lastflag;

    int t = blockIdx.x;
    int n = blockIdx.y;
    int tid = threadIdx.x;
    int w = tid >> 5, lane = tid & 31;

    int nt = g_nt[n];
    int pairs = nt * (nt + 1) / 2;
    bool active = (t < pairs);

    if (active) {
        int ti = 0, rem = t;
        while (rem >= nt - ti) { rem -= nt - ti; ti++; }
        int tj = ti + rem;
        int p0 = ti * TILE, q0 = tj * TILE;
        bool diag = (ti == tj);

        {
            int r = tid >> 2, c = tid & 3;
            int ip = g_idx[n][p0 + r];
            int iq = g_idx[n][q0 + r];
            *(uint4*)(sA + r * (ROWW * 2) + c * 16) = *(const uint4*)&g_sb[n][ip][c * 8];
            *(uint4*)(sB + r * (ROWW * 2) + c * 16) = *(const uint4*)&g_sb[n][iq][c * 8];
        }
        {
            float* qf = (float*)qpk;
            #pragma unroll
            for (int it = 0; it < 2; it++) {
                int idx = tid + it * 512;
                int q = idx >> 3, d = idx & 7;
                int iq = g_idx[n][q0 + q];
                float v = g_ppk[n][iq][d];
                if (d == 6 && diag) v = 0.0f;
                qf[(q >> 1) * (QROW * 2) + d * 2 + (q & 1)] = v;
            }
        }
        __syncthreads();

        int mstrip = w >> 1, nhalf = w & 1, lm4 = lane & 3;
        u32 sAu = smem_u32(sA), sBu = smem_u32(sB);

        u32 afr[2][4];
        {
            int arow = mstrip * 16 + (lane & 7) + ((lane >> 3) & 1) * 8;
            u32 aaddr = sAu + arow * (ROWW * 2) + (lane >> 4) * 16;
            LDMX4(afr[0], aaddr);
            LDMX4(afr[1], aaddr + 32);
        }
        u32 baddr = sBu + (nhalf * 64 + (lane & 7)) * (ROWW * 2) + (lane >> 3) * 16;

        int rowA0 = mstrip * 16 + (lane >> 2);
        int ip0 = g_idx[n][p0 + rowA0];
        int ip1 = g_idx[n][p0 + rowA0 + 8];
        u64 f0[2], f1[2], f2[2], f3[2], f4[2], sps[2], gp2[2];
        #pragma unroll
        for (int r = 0; r < 2; r++) {
            const float4* pf = (const float4*)&g_ppk[n][r ? ip1 : ip0][0];
            float4 pa = pf[0], pb = pf[1];
            f0[r] = pk2(pa.x, pa.x); f1[r] = pk2(pa.y, pa.y); f2[r] = pk2(pa.z, pa.z);
            f3[r] = pk2(pa.w, pa.w); f4[r] = pk2(pb.x, pb.x);
            sps[r] = pk2(pb.y, pb.y); gp2[r] = pk2(pb.z, pb.z);
        }
        u64 l2e = pk2(LOG2E, LOG2E);
        const char* qb = (const char*)qpk + (nhalf * 32 + lm4) * (QROW * 8);

        u64 accA = 0ull, accB = 0ull;

        #pragma unroll
        for (int tt = 0; tt < 8; tt++) {
            u32 bfr[4];
            LDMX4(bfr, baddr + tt * (8 * ROWW * 2));

            float d0 = 0.f, d1 = 0.f, d2_ = 0.f, d3 = 0.f;
            MMA16816(d0, d1, d2_, d3, afr[0][0], afr[0][1], afr[0][2], afr[0][3], bfr[0], bfr[1]);
            MMA16816(d0, d1, d2_, d3, afr[1][0], afr[1][1], afr[1][2], afr[1][3], bfr[2], bfr[3]);

            const char* qp = qb + tt * (4 * QROW * 8);
            ulonglong2 q01 = *(const ulonglong2*)(qp);
            ulonglong2 q23 = *(const ulonglong2*)(qp + 16);
            ulonglong2 q45 = *(const ulonglong2*)(qp + 32);
            ulonglong2 q67 = *(const ulonglong2*)(qp + 48);

            #pragma unroll
            for (int r = 0; r < 2; r++) {
                u64 dot;
                MUL2(dot, f0[r], q01.x);
                FMA2(dot, f1[r], q01.y, dot);
                FMA2(dot, f2[r], q23.x, dot);
                FMA2(dot, f3[r], q23.y, dot);
                FMA2(dot, f4[r], q45.x, dot);
                u64 s2; ADD2(s2, sps[r], q45.y);
                u64 t2; FMA2(t2, dot, l2e, s2);   // CEXP*d2 (<= ~1e-4)
                float tlo, thi; unpk2(t2, tlo, thi);
                u64 ee = pk2(ex2(tlo), ex2(thi));
                u64 cf; ADD2(cf, gp2[r], q67.x);
                u64 wv; MUL2(wv, ee, cf);
                u64 cc = r ? pk2(d2_, d3) : pk2(d0, d1);
                if (r) { FMA2(accB, wv, cc, accB); }
                else   { FMA2(accA, wv, cc, accA); }
            }
        }

        u64 acc2; ADD2(acc2, accA, accB);
        float alo, ahi; unpk2(acc2, alo, ahi);
        float acc = alo + ahi;

        #pragma unroll
        for (int o = 16; o > 0; o >>= 1) acc += __shfl_down_sync(0xffffffffu, acc, o);
        if (lane == 0) red[w] = acc;
        __syncthreads();
        if (tid == 0) {
            float s = 0.0f;
            #pragma unroll
            for (int v = 0; v < 16; v++) s += red[v];
            g_partial[n * NPAIR + t] = s;
            __threadfence();
            int v = atomicAdd(&g_ctr, 1);
            lastflag = (v == NIMG * NPAIR - 1);
        }
        __syncthreads();
    } else {
        if (tid == 0) {
            __threadfence();
            int v = atomicAdd(&g_ctr, 1);
            lastflag = (v == NIMG * NPAIR - 1);
        }
        __syncthreads();
    }

    if (lastflag) {
        float s = 0.0f;
        for (int i = tid; i < NIMG * NPAIR; i += 512) s += g_partial[i];
        #pragma unroll
        for (int o = 16; o > 0; o >>= 1) s += __shfl_down_sync(0xffffffffu, s, o);
        if (lane == 0) red[w] = s;
        __syncthreads();
        if (tid == 0) {
            float tot = 0.0f;
            #pragma unroll
            for (int v = 0; v < 16; v++) tot += red[v];
            out[0] = tot * (-1e-7f / (float)NIMG);   // WEIGHT * (-sum / N)
            g_ctr = 0;                               // reset for graph replay
        }
    }
}

// ---------------------------------------------------------------------------
extern "C" void kernel_launch(void* const* d_in, const int* in_sizes, int n_in,
                              void* d_out, int out_size)
{
    const float* images = (const float*)d_in[0];
    const float* segs   = (const float*)d_in[1];
    const float* rois   = (const float*)d_in[2];
    const int*   labels = (const int*)  d_in[3];

    prep_kernel<<<NIMG * 64 + NIMG, 256>>>(images, segs, rois, labels);
    dim3 grid(NPAIR, NIMG);
    energy_kernel<<<grid, 512>>>((float*)d_out);
}

// round 12
// speedup vs baseline: 2.6748x; 1.2947x over previous
#include <cuda_runtime.h>
#include <cuda_bf16.h>

#define NIMG  4
#define KCH   21
#define NPIX  4096      // 64*64
#define TILE  128
#define NPAIR 528       // max tile-pairs per image (partial-slot stride)
#define HW    16384     // 128*128
#define KPAD  64        // bf16 K row padding in global scratch
#define ROWW  40        // smem tile row width in bf16 (80B, conflict-free)
#define QROW  10        // qpk row stride in u64 (80B, 16B-aligned, conflict-free)
#define SVW   33        // transpose smem row stride (floats)
#define GRIDE 296       // persistent energy grid (2 CTAs x 148 SMs)

typedef unsigned long long u64;
typedef unsigned int       u32;

#define CEXP  (-0.72134752044448170f)   // -0.5 * log2(e)
#define LOG2E ( 1.44269504088896340f)

// ---- device scratch (rows [NPIX..NPIX+8) are never written => stay zero) ----
__device__ __nv_bfloat16 g_sb [NIMG][NPIX + 8][KPAD];
__device__ float         g_ppk[NIMG][NPIX + 8][8];   // f0..f4, CEXP*|f|^2, gate, 0
__device__ int           g_idx[NIMG][NPIX];          // compacted roi=1 pixel ids (+ sentinel pad)
__device__ int           g_nt [NIMG];                // tiles per image
__device__ float         g_partial[NIMG * NPAIR];
__device__ int           g_ctr;

// ---- packed f32x2 helpers ----
__device__ __forceinline__ u64 pk2(float lo, float hi) {
    u64 r; asm("mov.b64 %0, {%1, %2};" : "=l"(r) : "f"(lo), "f"(hi)); return r;
}
__device__ __forceinline__ void unpk2(u64 v, float& lo, float& hi) {
    asm("mov.b64 {%0, %1}, %2;" : "=f"(lo), "=f"(hi) : "l"(v));
}
#define FMA2(d, a, b, c) asm("fma.rn.f32x2 %0, %1, %2, %3;" : "=l"(d) : "l"(a), "l"(b), "l"(c))
#define MUL2(d, a, b)    asm("mul.rn.f32x2 %0, %1, %2;"     : "=l"(d) : "l"(a), "l"(b))
#define ADD2(d, a, b)    asm("add.rn.f32x2 %0, %1, %2;"     : "=l"(d) : "l"(a), "l"(b))
__device__ __forceinline__ float ex2(float x) {
    float r; asm("ex2.approx.f32 %0, %1;" : "=f"(r) : "f"(x)); return r;
}
__device__ __forceinline__ u32 smem_u32(const void* p) {
    u32 a; asm("{ .reg .u64 t; cvta.to.shared.u64 t, %1; cvt.u32.u64 %0, t; }" : "=r"(a) : "l"(p));
    return a;
}
__device__ __forceinline__ u32 bf16pair(float lo, float hi) {   // lo -> bits[0:16)
    u32 r; asm("cvt.rn.bf16x2.f32 %0, %1, %2;" : "=r"(r) : "f"(hi), "f"(lo)); return r;
}
#define LDMX4(r, addr) \
    asm volatile("ldmatrix.sync.aligned.m8n8.x4.shared.b16 {%0,%1,%2,%3}, [%4];" \
        : "=r"((r)[0]), "=r"((r)[1]), "=r"((r)[2]), "=r"((r)[3]) : "r"(addr))
#define MMA16816(d0,d1,d2,d3,a0,a1,a2,a3,b0,b1) \
    asm volatile("mma.sync.aligned.m16n8k16.row.col.f32.bf16.bf16.f32 " \
        "{%0,%1,%2,%3}, {%4,%5,%6,%7}, {%8,%9}, {%0,%1,%2,%3};" \
        : "+f"(d0), "+f"(d1), "+f"(d2), "+f"(d3) \
        : "r"(a0), "r"(a1), "r"(a2), "r"(a3), "r"(b0), "r"(b1))

// ---------------------------------------------------------------------------
// Kernel 1 (fused): blocks [0,256): coalesced transpose prep, one block per
// (n, y-row). blocks [256,260): per-image roi compaction (independent input).
// ---------------------------------------------------------------------------
__global__ __launch_bounds__(256) void prep_kernel(const float* __restrict__ images,
                                                   const float* __restrict__ segs,
                                                   const float* __restrict__ rois,
                                                   const int*   __restrict__ labels)
{
    __shared__ float sv[64][SVW];   // [x][k], k 21..31 zero
    __shared__ float sroi[64];
    __shared__ int   warp_sums[8];
    __shared__ int   s_cnt;

    int b = blockIdx.x;
    int tid = threadIdx.x;

    if (b < NIMG * 64) {
        // ================= PREP: one (n, y) row =================
        int n = b >> 6, y = b & 63;

        for (int i = tid; i < 64 * 11; i += 256) {
            int x = i / 11, k = 21 + (i % 11);
            sv[x][k] = 0.0f;
        }

        const float* segbase = segs + (size_t)n * KCH * HW + (2 * y) * 128;
        #pragma unroll
        for (int kb = 0; kb < 24; kb += 8) {
            int k = kb + (tid >> 5);
            int t = tid & 31;
            if (k < KCH) {
                const float* sp = segbase + (size_t)k * HW + 4 * t;
                float4 a0 = *(const float4*)sp;
                float4 a1 = *(const float4*)(sp + 128);
                sv[2 * t][k]     = 0.25f * ((a0.x + a0.y) + (a1.x + a1.y));
                sv[2 * t + 1][k] = 0.25f * ((a0.z + a0.w) + (a1.z + a1.w));
            }
        }
        if (tid < 64) sroi[tid] = rois[n * HW + 2 * y * 128 + 2 * tid];
        __syncthreads();

        {
            int x = tid >> 2, c = tid & 3;
            float roi = sroi[x];
            u32 wb[4];
            #pragma unroll
            for (int j = 0; j < 4; j++) {
                float v0 = sv[x][c * 8 + 2 * j]     * roi;
                float v1 = sv[x][c * 8 + 2 * j + 1] * roi;
                wb[j] = bf16pair(v0, v1);
            }
            *(uint4*)&g_sb[n][y * 64 + x][c * 8] = make_uint4(wb[0], wb[1], wb[2], wb[3]);
        }

        if (tid < 64) {
            int x = tid;
            float mx = sv[x][0];
            #pragma unroll
            for (int k = 1; k < KCH; k++) mx = fmaxf(mx, sv[x][k]);
            float roi = sroi[x];
            int p = y * 64 + x;
            int src = 2 * y * 128 + 2 * x;
            int lbl = labels[n * HW + src];
            float gate = fmaxf((lbl == 255) ? 1.0f : (roi - mx), 0.0f);

            const float* ib = images + (size_t)n * 3 * HW + src;
            float fx = (float)x * (1.0f / 50.0f);
            float fy = (float)y * (1.0f / 50.0f);
            float r  = ib[0]      * (1.0f / 15.0f);
            float g  = ib[HW]     * (1.0f / 15.0f);
            float bl = ib[2 * HW] * (1.0f / 15.0f);
            float sq = CEXP * (fx*fx + fy*fy + r*r + g*g + bl*bl);
            float4* pw = (float4*)&g_ppk[n][p][0];
            pw[0] = make_float4(fx, fy, r, g);
            pw[1] = make_float4(bl, sq, gate, 0.0f);
        }
    } else {
        // ================= COMPACT: one image =================
        int n = b - NIMG * 64;
        int lane = tid & 31, w = tid >> 5;
        int pbase = tid * 16;

        u32 mask = 0; int c = 0;
        #pragma unroll
        for (int i = 0; i < 16; i++) {
            int p = pbase + i;
            int y = p >> 6, x = p & 63;
            float r = rois[n * HW + (2 * y) * 128 + 2 * x];
            if (r > 0.5f) { mask |= (1u << i); c++; }
        }
        int sc = c;
        #pragma unroll
        for (int o = 1; o < 32; o <<= 1) {
            int v = __shfl_up_sync(0xffffffffu, sc, o);
            if (lane >= o) sc += v;
        }
        if (lane == 31) warp_sums[w] = sc;
        __syncthreads();
        int wb = 0;
        #pragma unroll
        for (int i = 0; i < 8; i++) if (i < w) wb += warp_sums[i];
        int pos = wb + sc - c;
        #pragma unroll
        for (int i = 0; i < 16; i++)
            if (mask & (1u << i)) g_idx[n][pos++] = pbase + i;
        if (tid == 255) s_cnt = wb + sc;
        __syncthreads();
        int cnt = s_cnt;
        int nt = (cnt + 127) >> 7;
        for (int j = cnt + tid; j < nt * 128; j += 256) g_idx[n][j] = NPIX;  // sentinel
        if (tid == 0) g_nt[n] = nt;
    }
}

// ---------------------------------------------------------------------------
// Kernel 2: persistent CTAs, static item stride over all (n, tile-pair).
// Math core identical to R11.
// ---------------------------------------------------------------------------
__global__ __launch_bounds__(512, 2) void energy_kernel(float* __restrict__ out)
{
    __shared__ __align__(16) char sA[TILE * ROWW * 2];
    __shared__ __align__(16) char sB[TILE * ROWW * 2];
    __shared__ __align__(16) u64  qpk[64][QROW];
    __shared__ float red[16];
    __shared__ int   lastflag;

    int tid = threadIdx.x;
    int w = tid >> 5, lane = tid & 31;

    // pairs prefix (uniform per CTA)
    int pre[NIMG + 1];
    pre[0] = 0;
    #pragma unroll
    for (int i = 0; i < NIMG; i++) {
        int nt = g_nt[i];
        pre[i + 1] = pre[i] + nt * (nt + 1) / 2;
    }
    int total = pre[NIMG];

    for (int m = blockIdx.x; m < total; m += GRIDE) {
        __syncthreads();   // previous item's smem reads complete

        int n = 0;
        #pragma unroll
        for (int i = 1; i < NIMG; i++) if (m >= pre[i]) n = i;
        int t  = m - pre[n];
        int nt = g_nt[n];

        int ti = 0, rem = t;
        while (rem >= nt - ti) { rem -= nt - ti; ti++; }
        int tj = ti + rem;
        int p0 = ti * TILE, q0 = tj * TILE;
        bool diag = (ti == tj);

        {
            int r = tid >> 2, c = tid & 3;
            int ip = g_idx[n][p0 + r];
            int iq = g_idx[n][q0 + r];
            *(uint4*)(sA + r * (ROWW * 2) + c * 16) = *(const uint4*)&g_sb[n][ip][c * 8];
            *(uint4*)(sB + r * (ROWW * 2) + c * 16) = *(const uint4*)&g_sb[n][iq][c * 8];
        }
        {
            float* qf = (float*)qpk;
            #pragma unroll
            for (int it = 0; it < 2; it++) {
                int idx = tid + it * 512;
                int q = idx >> 3, d = idx & 7;
                int iq = g_idx[n][q0 + q];
                float v = g_ppk[n][iq][d];
                if (d == 6 && diag) v = 0.0f;
                qf[(q >> 1) * (QROW * 2) + d * 2 + (q & 1)] = v;
            }
        }
        __syncthreads();

        int mstrip = w >> 1, nhalf = w & 1, lm4 = lane & 3;
        u32 sAu = smem_u32(sA), sBu = smem_u32(sB);

        u32 afr[2][4];
        {
            int arow = mstrip * 16 + (lane & 7) + ((lane >> 3) & 1) * 8;
            u32 aaddr = sAu + arow * (ROWW * 2) + (lane >> 4) * 16;
            LDMX4(afr[0], aaddr);
            LDMX4(afr[1], aaddr + 32);
        }
        u32 baddr = sBu + (nhalf * 64 + (lane & 7)) * (ROWW * 2) + (lane >> 3) * 16;

        int rowA0 = mstrip * 16 + (lane >> 2);
        int ip0 = g_idx[n][p0 + rowA0];
        int ip1 = g_idx[n][p0 + rowA0 + 8];
        u64 f0[2], f1[2], f2[2], f3[2], f4[2], sps[2], gp2[2];
        #pragma unroll
        for (int r = 0; r < 2; r++) {
            const float4* pf = (const float4*)&g_ppk[n][r ? ip1 : ip0][0];
            float4 pa = pf[0], pb = pf[1];
            f0[r] = pk2(pa.x, pa.x); f1[r] = pk2(pa.y, pa.y); f2[r] = pk2(pa.z, pa.z);
            f3[r] = pk2(pa.w, pa.w); f4[r] = pk2(pb.x, pb.x);
            sps[r] = pk2(pb.y, pb.y); gp2[r] = pk2(pb.z, pb.z);
        }
        u64 l2e = pk2(LOG2E, LOG2E);
        const char* qb = (const char*)qpk + (nhalf * 32 + lm4) * (QROW * 8);

        u64 accA = 0ull, accB = 0ull;

        #pragma unroll
        for (int tt = 0; tt < 8; tt++) {
            u32 bfr[4];
            LDMX4(bfr, baddr + tt * (8 * ROWW * 2));

            float d0 = 0.f, d1 = 0.f, d2_ = 0.f, d3 = 0.f;
            MMA16816(d0, d1, d2_, d3, afr[0][0], afr[0][1], afr[0][2], afr[0][3], bfr[0], bfr[1]);
            MMA16816(d0, d1, d2_, d3, afr[1][0], afr[1][1], afr[1][2], afr[1][3], bfr[2], bfr[3]);

            const char* qp = qb + tt * (4 * QROW * 8);
            ulonglong2 q01 = *(const ulonglong2*)(qp);
            ulonglong2 q23 = *(const ulonglong2*)(qp + 16);
            ulonglong2 q45 = *(const ulonglong2*)(qp + 32);
            ulonglong2 q67 = *(const ulonglong2*)(qp + 48);

            #pragma unroll
            for (int r = 0; r < 2; r++) {
                u64 dot;
                MUL2(dot, f0[r], q01.x);
                FMA2(dot, f1[r], q01.y, dot);
                FMA2(dot, f2[r], q23.x, dot);
                FMA2(dot, f3[r], q23.y, dot);
                FMA2(dot, f4[r], q45.x, dot);
                u64 s2; ADD2(s2, sps[r], q45.y);
                u64 t2; FMA2(t2, dot, l2e, s2);   // CEXP*d2 (<= ~1e-4)
                float tlo, thi; unpk2(t2, tlo, thi);
                u64 ee = pk2(ex2(tlo), ex2(thi));
                u64 cf; ADD2(cf, gp2[r], q67.x);
                u64 wv; MUL2(wv, ee, cf);
                u64 cc = r ? pk2(d2_, d3) : pk2(d0, d1);
                if (r) { FMA2(accB, wv, cc, accB); }
                else   { FMA2(accA, wv, cc, accA); }
            }
        }

        u64 acc2; ADD2(acc2, accA, accB);
        float alo, ahi; unpk2(acc2, alo, ahi);
        float acc = alo + ahi;

        #pragma unroll
        for (int o = 16; o > 0; o >>= 1) acc += __shfl_down_sync(0xffffffffu, acc, o);
        if (lane == 0) red[w] = acc;
        __syncthreads();
        if (tid == 0) {
            float s = 0.0f;
            #pragma unroll
            for (int v = 0; v < 16; v++) s += red[v];
            g_partial[m] = s;
        }
    }

    // ---- per-CTA completion; last CTA reduces ----
    if (tid == 0) {
        __threadfence();
        int v = atomicAdd(&g_ctr, 1);
        lastflag = (v == GRIDE - 1);
    }
    __syncthreads();

    if (lastflag) {
        float s = 0.0f;
        for (int i = tid; i < total; i += 512) s += g_partial[i];
        #pragma unroll
        for (int o = 16; o > 0; o >>= 1) s += __shfl_down_sync(0xffffffffu, s, o);
        if (lane == 0) red[w] = s;
        __syncthreads();
        if (tid == 0) {
            float tot = 0.0f;
            #pragma unroll
            for (int v = 0; v < 16; v++) tot += red[v];
            out[0] = tot * (-1e-7f / (float)NIMG);   // WEIGHT * (-sum / N)
            g_ctr = 0;                               // reset for graph replay
        }
    }
}

// ---------------------------------------------------------------------------
extern "C" void kernel_launch(void* const* d_in, const int* in_sizes, int n_in,
                              void* d_out, int out_size)
{
    const float* images = (const float*)d_in[0];
    const float* segs   = (const float*)d_in[1];
    const float* rois   = (const float*)d_in[2];
    const int*   labels = (const int*)  d_in[3];

    prep_kernel<<<NIMG * 64 + NIMG, 256>>>(images, segs, rois, labels);
    energy_kernel<<<GRIDE, 512>>>((float*)d_out);
}

// round 13
// speedup vs baseline: 2.9645x; 1.1083x over previous
#include <cuda_runtime.h>
#include <cuda_bf16.h>

#define NIMG  4
#define KCH   21
#define NPIX  4096      // 64*64
#define TILE  128
#define NPAIR 528       // max tile-pairs per image (partial-slot stride)
#define HW    16384     // 128*128
#define KPAD  64        // bf16 K row padding in global scratch
#define ROWW  40        // seg smem row width in bf16 (80B, conflict-free)
#define FROW  48        // feat smem row bytes (conflict-free ldmatrix)
#define SVW   33        // transpose smem row stride (floats)
#define GRIDE 296       // persistent energy grid (2 CTAs x 148 SMs)

typedef unsigned long long u64;
typedef unsigned int       u32;
typedef unsigned short     u16;

#define CEXP  (-0.72134752044448170f)   // -0.5 * log2(e)
#define LOG2E ( 1.44269504088896340f)

// ---- device scratch (rows [NPIX..NPIX+8) never written => stay zero) ----
__device__ __nv_bfloat16 g_sb[NIMG][NPIX + 8][KPAD]; // seg*roi bf16, k 21..31 zero
__device__ u32   g_fA[NIMG][NPIX + 8][8];            // bf16 row [hi(5),hi(5),lo(5),0]
__device__ u32   g_fB[NIMG][NPIX + 8][8];            // bf16 row [hi(5),lo(5),hi(5),0]
__device__ float g_pq[NIMG][NPIX + 8][2];            // (CEXP*|f|^2, gate)
__device__ int   g_idx[NIMG][NPIX];                  // compacted roi=1 pixel ids
__device__ int   g_nt [NIMG];
__device__ float g_partial[NIMG * NPAIR];
__device__ int   g_ctr;

// ---- packed f32x2 helpers ----
__device__ __forceinline__ u64 pk2(float lo, float hi) {
    u64 r; asm("mov.b64 %0, {%1, %2};" : "=l"(r) : "f"(lo), "f"(hi)); return r;
}
__device__ __forceinline__ void unpk2(u64 v, float& lo, float& hi) {
    asm("mov.b64 {%0, %1}, %2;" : "=f"(lo), "=f"(hi) : "l"(v));
}
#define FMA2(d, a, b, c) asm("fma.rn.f32x2 %0, %1, %2, %3;" : "=l"(d) : "l"(a), "l"(b), "l"(c))
#define MUL2(d, a, b)    asm("mul.rn.f32x2 %0, %1, %2;"     : "=l"(d) : "l"(a), "l"(b))
#define ADD2(d, a, b)    asm("add.rn.f32x2 %0, %1, %2;"     : "=l"(d) : "l"(a), "l"(b))
__device__ __forceinline__ float ex2(float x) {
    float r; asm("ex2.approx.f32 %0, %1;" : "=f"(r) : "f"(x)); return r;
}
__device__ __forceinline__ u32 smem_u32(const void* p) {
    u32 a; asm("{ .reg .u64 t; cvta.to.shared.u64 t, %1; cvt.u32.u64 %0, t; }" : "=r"(a) : "l"(p));
    return a;
}
__device__ __forceinline__ u32 bf16pair(float lo, float hi) {   // lo -> bits[0:16)
    u32 r; asm("cvt.rn.bf16x2.f32 %0, %1, %2;" : "=r"(r) : "f"(hi), "f"(lo)); return r;
}
#define LDMX4(r, addr) \
    asm volatile("ldmatrix.sync.aligned.m8n8.x4.shared.b16 {%0,%1,%2,%3}, [%4];" \
        : "=r"((r)[0]), "=r"((r)[1]), "=r"((r)[2]), "=r"((r)[3]) : "r"(addr))
#define MMA16816(d0,d1,d2,d3,a0,a1,a2,a3,b0,b1) \
    asm volatile("mma.sync.aligned.m16n8k16.row.col.f32.bf16.bf16.f32 " \
        "{%0,%1,%2,%3}, {%4,%5,%6,%7}, {%8,%9}, {%0,%1,%2,%3};" \
        : "+f"(d0), "+f"(d1), "+f"(d2), "+f"(d3) \
        : "r"(a0), "r"(a1), "r"(a2), "r"(a3), "r"(b0), "r"(b1))

// ---------------------------------------------------------------------------
// Kernel 1 (fused): blocks [0,256): coalesced transpose prep; [256,260): compact.
// ---------------------------------------------------------------------------
__global__ __launch_bounds__(256) void prep_kernel(const float* __restrict__ images,
                                                   const float* __restrict__ segs,
                                                   const float* __restrict__ rois,
                                                   const int*   __restrict__ labels)
{
    __shared__ float sv[64][SVW];
    __shared__ float sroi[64];
    __shared__ int   warp_sums[8];
    __shared__ int   s_cnt;

    int b = blockIdx.x;
    int tid = threadIdx.x;

    if (b < NIMG * 64) {
        int n = b >> 6, y = b & 63;

        for (int i = tid; i < 64 * 11; i += 256) {
            int x = i / 11, k = 21 + (i % 11);
            sv[x][k] = 0.0f;
        }

        const float* segbase = segs + (size_t)n * KCH * HW + (2 * y) * 128;
        #pragma unroll
        for (int kb = 0; kb < 24; kb += 8) {
            int k = kb + (tid >> 5);
            int t = tid & 31;
            if (k < KCH) {
                const float* sp = segbase + (size_t)k * HW + 4 * t;
                float4 a0 = *(const float4*)sp;
                float4 a1 = *(const float4*)(sp + 128);
                sv[2 * t][k]     = 0.25f * ((a0.x + a0.y) + (a1.x + a1.y));
                sv[2 * t + 1][k] = 0.25f * ((a0.z + a0.w) + (a1.z + a1.w));
            }
        }
        if (tid < 64) sroi[tid] = rois[n * HW + 2 * y * 128 + 2 * tid];
        __syncthreads();

        {
            int x = tid >> 2, c = tid & 3;
            float roi = sroi[x];
            u32 wb[4];
            #pragma unroll
            for (int j = 0; j < 4; j++) {
                float v0 = sv[x][c * 8 + 2 * j]     * roi;
                float v1 = sv[x][c * 8 + 2 * j + 1] * roi;
                wb[j] = bf16pair(v0, v1);
            }
            *(uint4*)&g_sb[n][y * 64 + x][c * 8] = make_uint4(wb[0], wb[1], wb[2], wb[3]);
        }

        if (tid < 64) {
            int x = tid;
            float mx = sv[x][0];
            #pragma unroll
            for (int k = 1; k < KCH; k++) mx = fmaxf(mx, sv[x][k]);
            float roi = sroi[x];
            int p = y * 64 + x;
            int src = 2 * y * 128 + 2 * x;
            int lbl = labels[n * HW + src];
            float gate = fmaxf((lbl == 255) ? 1.0f : (roi - mx), 0.0f);

            const float* ib = images + (size_t)n * 3 * HW + src;
            float f[5];
            f[0] = (float)x * (1.0f / 50.0f);
            f[1] = (float)y * (1.0f / 50.0f);
            f[2] = ib[0]      * (1.0f / 15.0f);
            f[3] = ib[HW]     * (1.0f / 15.0f);
            f[4] = ib[2 * HW] * (1.0f / 15.0f);
            float sq = f[0]*f[0] + f[1]*f[1] + f[2]*f[2] + f[3]*f[3] + f[4]*f[4];
            *(float2*)&g_pq[n][p][0] = make_float2(CEXP * sq, gate);

            u16 h[5], l[5];
            #pragma unroll
            for (int d = 0; d < 5; d++) {
                __nv_bfloat16 hb = __float2bfloat16(f[d]);
                __nv_bfloat16 lb = __float2bfloat16(f[d] - __bfloat162float(hb));
                h[d] = *(u16*)&hb; l[d] = *(u16*)&lb;
            }
            // A row: hi(5) hi(5) lo(5) 0  |  B row: hi(5) lo(5) hi(5) 0
            u32 aw[8], bw[8];
            aw[0] = h[0] | (u32)h[1] << 16;  aw[1] = h[2] | (u32)h[3] << 16;
            aw[2] = h[4] | (u32)h[0] << 16;  aw[3] = h[1] | (u32)h[2] << 16;
            aw[4] = h[3] | (u32)h[4] << 16;  aw[5] = l[0] | (u32)l[1] << 16;
            aw[6] = l[2] | (u32)l[3] << 16;  aw[7] = l[4];
            bw[0] = h[0] | (u32)h[1] << 16;  bw[1] = h[2] | (u32)h[3] << 16;
            bw[2] = h[4] | (u32)l[0] << 16;  bw[3] = l[1] | (u32)l[2] << 16;
            bw[4] = l[3] | (u32)l[4] << 16;  bw[5] = h[0] | (u32)h[1] << 16;
            bw[6] = h[2] | (u32)h[3] << 16;  bw[7] = h[4];
            *(uint4*)&g_fA[n][p][0] = make_uint4(aw[0], aw[1], aw[2], aw[3]);
            *(uint4*)&g_fA[n][p][4] = make_uint4(aw[4], aw[5], aw[6], aw[7]);
            *(uint4*)&g_fB[n][p][0] = make_uint4(bw[0], bw[1], bw[2], bw[3]);
            *(uint4*)&g_fB[n][p][4] = make_uint4(bw[4], bw[5], bw[6], bw[7]);
        }
    } else {
        int n = b - NIMG * 64;
        int lane = tid & 31, w = tid >> 5;
        int pbase = tid * 16;

        u32 mask = 0; int c = 0;
        #pragma unroll
        for (int i = 0; i < 16; i++) {
            int p = pbase + i;
            int y = p >> 6, x = p & 63;
            float r = rois[n * HW + (2 * y) * 128 + 2 * x];
            if (r > 0.5f) { mask |= (1u << i); c++; }
        }
        int sc = c;
        #pragma unroll
        for (int o = 1; o < 32; o <<= 1) {
            int v = __shfl_up_sync(0xffffffffu, sc, o);
            if (lane >= o) sc += v;
        }
        if (lane == 31) warp_sums[w] = sc;
        __syncthreads();
        int wb = 0;
        #pragma unroll
        for (int i = 0; i < 8; i++) if (i < w) wb += warp_sums[i];
        int pos = wb + sc - c;
        #pragma unroll
        for (int i = 0; i < 16; i++)
            if (mask & (1u << i)) g_idx[n][pos++] = pbase + i;
        if (tid == 255) s_cnt = wb + sc;
        __syncthreads();
        int cnt = s_cnt;
        int nt = (cnt + 127) >> 7;
        for (int j = cnt + tid; j < nt * 128; j += 256) g_idx[n][j] = NPIX;  // sentinel
        if (tid == 0) g_nt[n] = nt;
    }
}

// ---------------------------------------------------------------------------
// Kernel 2: persistent CTAs; seg GEMM (K=32) + feature-dot GEMM (K=16 hi/lo)
// both on tensor pipe; scalar work = exp + gating only.
// ---------------------------------------------------------------------------
__global__ __launch_bounds__(512, 2) void energy_kernel(float* __restrict__ out)
{
    __shared__ __align__(16) char sA [TILE * ROWW * 2];
    __shared__ __align__(16) char sB [TILE * ROWW * 2];
    __shared__ __align__(16) char sFA[TILE * FROW];
    __shared__ __align__(16) char sFB[TILE * FROW];
    __shared__ __align__(16) u64  qsg[64][2];     // (sqs pair, gate pair)
    __shared__ float red[16];
    __shared__ int   lastflag;

    int tid = threadIdx.x;
    int w = tid >> 5, lane = tid & 31;

    int pre[NIMG + 1];
    pre[0] = 0;
    #pragma unroll
    for (int i = 0; i < NIMG; i++) {
        int nt = g_nt[i];
        pre[i + 1] = pre[i] + nt * (nt + 1) / 2;
    }
    int total = pre[NIMG];

    for (int m = blockIdx.x; m < total; m += GRIDE) {
        __syncthreads();   // previous item's smem reads complete

        int n = 0;
        #pragma unroll
        for (int i = 1; i < NIMG; i++) if (m >= pre[i]) n = i;
        int t  = m - pre[n];
        int nt = g_nt[n];

        int ti = 0, rem = t;
        while (rem >= nt - ti) { rem -= nt - ti; ti++; }
        int tj = ti + rem;
        int p0 = ti * TILE, q0 = tj * TILE;
        bool diag = (ti == tj);

        // ---- seg tiles ----
        {
            int r = tid >> 2, c = tid & 3;
            int ip = g_idx[n][p0 + r];
            int iq = g_idx[n][q0 + r];
            *(uint4*)(sA + r * (ROWW * 2) + c * 16) = *(const uint4*)&g_sb[n][ip][c * 8];
            *(uint4*)(sB + r * (ROWW * 2) + c * 16) = *(const uint4*)&g_sb[n][iq][c * 8];
        }
        // ---- feature tiles ----
        if (tid < 256) {
            int r = tid >> 1, h = tid & 1;
            int ip = g_idx[n][p0 + r];
            *(uint4*)(sFA + r * FROW + h * 16) = *(const uint4*)&g_fA[n][ip][h * 4];
        } else {
            int r = (tid - 256) >> 1, h = tid & 1;
            int iq = g_idx[n][q0 + r];
            *(uint4*)(sFB + r * FROW + h * 16) = *(const uint4*)&g_fB[n][iq][h * 4];
        }
        // ---- q-side scalars: (sqs pair, gate pair), diag zeroes gate ----
        if (tid < 64) {
            int iq0 = g_idx[n][q0 + 2 * tid];
            int iq1 = g_idx[n][q0 + 2 * tid + 1];
            float2 e = *(const float2*)&g_pq[n][iq0][0];
            float2 o = *(const float2*)&g_pq[n][iq1][0];
            qsg[tid][0] = pk2(e.x, o.x);
            qsg[tid][1] = pk2(diag ? 0.0f : e.y, diag ? 0.0f : o.y);
        }
        __syncthreads();

        int mstrip = w >> 1, nhalf = w & 1, lm4 = lane & 3;
        u32 sAu = smem_u32(sA), sBu = smem_u32(sB);
        u32 sFAu = smem_u32(sFA), sFBu = smem_u32(sFB);

        // A fragments (seg K=32, feat K=16)
        u32 afr[2][4], afeat[4];
        {
            int arow = mstrip * 16 + (lane & 7) + ((lane >> 3) & 1) * 8;
            u32 aaddr = sAu + arow * (ROWW * 2) + (lane >> 4) * 16;
            LDMX4(afr[0], aaddr);
            LDMX4(afr[1], aaddr + 32);
            u32 faddr = sFAu + arow * FROW + ((lane >> 4) & 1) * 16;
            LDMX4(afeat, faddr);
        }
        u32 baddr  = sBu  + (nhalf * 64 + (lane & 7)) * (ROWW * 2) + (lane >> 3) * 16;
        u32 fbaddr = sFBu + (nhalf * 64 + (lane & 7) + ((lane >> 4) & 1) * 8) * FROW
                          + ((lane >> 3) & 1) * 16;

        // p-side scalars (packed broadcast)
        int rowA0 = mstrip * 16 + (lane >> 2);
        int ip0 = g_idx[n][p0 + rowA0];
        int ip1 = g_idx[n][p0 + rowA0 + 8];
        u64 sps[2], gp2[2];
        {
            float2 pp0 = *(const float2*)&g_pq[n][ip0][0];
            float2 pp1 = *(const float2*)&g_pq[n][ip1][0];
            sps[0] = pk2(pp0.x, pp0.x); gp2[0] = pk2(pp0.y, pp0.y);
            sps[1] = pk2(pp1.x, pp1.x); gp2[1] = pk2(pp1.y, pp1.y);
        }
        u64 l2e = pk2(LOG2E, LOG2E);
        u64 accA = 0ull, accB = 0ull;
        u32 bfeat[4];

        #pragma unroll
        for (int tt = 0; tt < 8; tt++) {
            u32 bfr[4];
            LDMX4(bfr, baddr + tt * (8 * ROWW * 2));
            if ((tt & 1) == 0) LDMX4(bfeat, fbaddr + tt * (8 * FROW));
            u32 b0f = (tt & 1) ? bfeat[2] : bfeat[0];
            u32 b1f = (tt & 1) ? bfeat[3] : bfeat[1];

            float d0 = 0.f, d1 = 0.f, d2_ = 0.f, d3 = 0.f;
            MMA16816(d0, d1, d2_, d3, afr[0][0], afr[0][1], afr[0][2], afr[0][3], bfr[0], bfr[1]);
            MMA16816(d0, d1, d2_, d3, afr[1][0], afr[1][1], afr[1][2], afr[1][3], bfr[2], bfr[3]);
            float e0 = 0.f, e1 = 0.f, e2 = 0.f, e3 = 0.f;
            MMA16816(e0, e1, e2, e3, afeat[0], afeat[1], afeat[2], afeat[3], b0f, b1f);

            ulonglong2 qv = *(const ulonglong2*)&qsg[nhalf * 32 + tt * 4 + lm4][0];

            #pragma unroll
            for (int r = 0; r < 2; r++) {
                u64 dotp = r ? pk2(e2, e3) : pk2(e0, e1);
                u64 s2; ADD2(s2, sps[r], qv.x);
                u64 t2; FMA2(t2, dotp, l2e, s2);   // CEXP*d2 (<= ~0 + eps)
                float tlo, thi; unpk2(t2, tlo, thi);
                u64 ee = pk2(ex2(tlo), ex2(thi));
                u64 cf; ADD2(cf, gp2[r], qv.y);    // q-gate zeroed on diag
                u64 wv; MUL2(wv, ee, cf);
                u64 cc = r ? pk2(d2_, d3) : pk2(d0, d1);
                if (r) { FMA2(accB, wv, cc, accB); }
                else   { FMA2(accA, wv, cc, accA); }
            }
        }

        u64 acc2; ADD2(acc2, accA, accB);
        float alo, ahi; unpk2(acc2, alo, ahi);
        float acc = alo + ahi;

        #pragma unroll
        for (int o = 16; o > 0; o >>= 1) acc += __shfl_down_sync(0xffffffffu, acc, o);
        if (lane == 0) red[w] = acc;
        __syncthreads();
        if (tid == 0) {
            float s = 0.0f;
            #pragma unroll
            for (int v = 0; v < 16; v++) s += red[v];
            g_partial[m] = s;
        }
    }

    // ---- per-CTA completion; last CTA reduces ----
    if (tid == 0) {
        __threadfence();
        int v = atomicAdd(&g_ctr, 1);
        lastflag = (v == GRIDE - 1);
    }
    __syncthreads();

    if (lastflag) {
        float s = 0.0f;
        for (int i = tid; i < total; i += 512) s += g_partial[i];
        #pragma unroll
        for (int o = 16; o > 0; o >>= 1) s += __shfl_down_sync(0xffffffffu, s, o);
        if (lane == 0) red[w] = s;
        __syncthreads();
        if (tid == 0) {
            float tot = 0.0f;
            #pragma unroll
            for (int v = 0; v < 16; v++) tot += red[v];
            out[0] = tot * (-1e-7f / (float)NIMG);   // WEIGHT * (-sum / N)
            g_ctr = 0;                               // reset for graph replay
        }
    }
}

// ---------------------------------------------------------------------------
extern "C" void kernel_launch(void* const* d_in, const int* in_sizes, int n_in,
                              void* d_out, int out_size)
{
    const float* images = (const float*)d_in[0];
    const float* segs   = (const float*)d_in[1];
    const float* rois   = (const float*)d_in[2];
    const int*   labels = (const int*)  d_in[3];

    prep_kernel<<<NIMG * 64 + NIMG, 256>>>(images, segs, rois, labels);
    energy_kernel<<<GRIDE, 512>>>((float*)d_out);
}